// round 11
// baseline (speedup 1.0000x reference)
#include <cuda_runtime.h>

typedef unsigned int u32;

#define Sc 4096
#define Dc 64
#define BHc 64
#define NCHUNK 16
#define CHUNK (Sc/NCHUNK)   // 256
#define NB (CHUNK/32)       // 8 blocks of 32 s-rows

__device__ float g_pKV[NCHUNK][BHc][Dc*Dc];  // f32 partial KV
__device__ float g_pKs[NCHUNK][BHc][Dc];     // f32 partial Ksum
__device__ float g_KV[BHc][Dc*Dc];           // reduced KV (f32)
__device__ float g_Ks[BHc][Dc];              // reduced Ksum (f32)

__device__ __forceinline__ u32 to_tf32(float f){
    u32 r; asm("cvt.rna.tf32.f32 %0, %1;" : "=r"(r) : "f"(f)); return r;
}
__device__ __forceinline__ void mma8(float c[4], u32 a0, u32 a1, u32 a2, u32 a3,
                                     u32 b0, u32 b1){
    asm volatile("mma.sync.aligned.m16n8k8.row.col.f32.tf32.tf32.f32 "
        "{%0,%1,%2,%3}, {%4,%5,%6,%7}, {%8,%9}, {%0,%1,%2,%3};"
        : "+f"(c[0]), "+f"(c[1]), "+f"(c[2]), "+f"(c[3])
        : "r"(a0), "r"(a1), "r"(a2), "r"(a3), "r"(b0), "r"(b1));
}
__device__ __forceinline__ float feat(float x){
    return x > 0.f ? x + 1.f : __expf(x);
}
__device__ __forceinline__ u32 smem_u32(const void* p){
    u32 a; asm("{ .reg .u64 t; cvta.to.shared.u64 t, %1; cvt.u32.u64 %0, t; }" : "=r"(a) : "l"(p));
    return a;
}
__device__ __forceinline__ void cp16(u32 dst, const float* src){
    asm volatile("cp.async.cg.shared.global [%0], [%1], 16;" :: "r"(dst), "l"(src) : "memory");
}
#define CP_COMMIT() asm volatile("cp.async.commit_group;" ::: "memory")

// ---------------------------------------------------------------------------
// Phase 1: partial KV[d][e] = sum_s Kf[s][d] V[s][e] (+Ksum via const ones
// fragment). grid (BHc, NCHUNK), 256 threads = 8 warps.
// Warp w: d-tile (w>>1)*16, n-half w&1 (half0: nt {0,1,2,3}+Ksum, half1: {4..7}).
// K: triple-buffered cp.async + staging-time RNA convert (feat*mask fused).
// V: DIRECT __ldg B-fragments (raw bits = RZ; sector-perfect 4x32B per LDG).
// ---------------------------------------------------------------------------
__global__ __launch_bounds__(256, 5) void phase1_kernel(const float* __restrict__ K,
                                                        const float* __restrict__ V,
                                                        const float* __restrict__ M){
    __shared__ __align__(16) u32 sK[3][32][72];   // raw f32 -> tf32 bits in place

    const int bh = blockIdx.x, ch = blockIdx.y;
    const int t = threadIdx.x;
    const int warp = t >> 5, lane = t & 31;
    const int g = lane >> 2, tig = lane & 3;

    const float* Kp = K + ((size_t)bh*Sc + (size_t)ch*CHUNK)*Dc;
    const float* Vp = V + ((size_t)bh*Sc + (size_t)ch*CHUNK)*Dc;
    const float* Mp = M + (size_t)bh*Sc + (size_t)ch*CHUNK;

    const int srow = t >> 3;          // 0..31
    const int c4a = (t & 7) * 4;      // first 16B chunk col
    const int c4b = c4a + 32;         // second chunk col
    const u32 skb = smem_u32(&sK[0][0][0]);
    const u32 BUFB = 32*72*4;

    // prologue: prefetch K blocks 0,1
    #pragma unroll
    for (int b = 0; b < 2; b++){
        const float* kr = Kp + (size_t)(b*32 + srow)*Dc;
        const u32 kd = skb + b*BUFB + (srow*72)*4;
        cp16(kd + c4a*4, kr + c4a);
        cp16(kd + c4b*4, kr + c4b);
        CP_COMMIT();
    }

    float acc[5][4];
    #pragma unroll
    for (int n = 0; n < 5; n++)
        #pragma unroll
        for (int i = 0; i < 4; i++) acc[n][i] = 0.f;

    const int d0 = (warp >> 1) * 16;
    const int nh = warp & 1;
    // constant ones-tile B fragment (col 64 of virtual [V|1] matrix)
    const u32 bone = (g == 0) ? 0x3F800000u : 0u;

    #pragma unroll
    for (int b = 0; b < NB; b++){
        const int buf = b % 3;
        asm volatile("cp.async.wait_group 1;" ::: "memory");
        __syncthreads();

        // prefetch K block b+2 into buf (b+2)%3 (= buf of b-1; safe post-sync)
        if (b + 2 < NB){
            const float* kr = Kp + (size_t)((b+2)*32 + srow)*Dc;
            const u32 kd = skb + ((b+2)%3)*BUFB + (srow*72)*4;
            cp16(kd + c4a*4, kr + c4a);
            cp16(kd + c4b*4, kr + c4b);
        }
        CP_COMMIT();   // uniform commit keeps group accounting simple

        // staging convert: K only (feat*mask, RNA), in place
        {
            const float m = __ldg(Mp + b*32 + srow);
            u32* ka = &sK[buf][srow][c4a];
            u32* kb = &sK[buf][srow][c4b];
            uint4 kx = *(uint4*)ka, ky = *(uint4*)kb;
            *(uint4*)ka = make_uint4(to_tf32(feat(__uint_as_float(kx.x))*m),
                                     to_tf32(feat(__uint_as_float(kx.y))*m),
                                     to_tf32(feat(__uint_as_float(kx.z))*m),
                                     to_tf32(feat(__uint_as_float(kx.w))*m));
            *(uint4*)kb = make_uint4(to_tf32(feat(__uint_as_float(ky.x))*m),
                                     to_tf32(feat(__uint_as_float(ky.y))*m),
                                     to_tf32(feat(__uint_as_float(ky.z))*m),
                                     to_tf32(feat(__uint_as_float(ky.w))*m));
        }
        __syncthreads();

        // MMA: A from smem K, B via direct LDG from V (RZ), ones via constant
        const float* vB = Vp + (size_t)(b*32)*Dc;
        #pragma unroll
        for (int ks = 0; ks < 4; ks++){
            const int s0 = ks*8;
            u32 a0 = sK[buf][s0+tig  ][d0+g  ];
            u32 a1 = sK[buf][s0+tig  ][d0+g+8];
            u32 a2 = sK[buf][s0+tig+4][d0+g  ];
            u32 a3 = sK[buf][s0+tig+4][d0+g+8];
            const float* vlo = vB + (size_t)(s0+tig  )*Dc + g;
            const float* vhi = vB + (size_t)(s0+tig+4)*Dc + g;
            #pragma unroll
            for (int i = 0; i < 4; i++){
                const int e = (nh*4 + i)*8;
                u32 b0 = __float_as_uint(__ldg(vlo + e));
                u32 b1 = __float_as_uint(__ldg(vhi + e));
                mma8(acc[i], a0, a1, a2, a3, b0, b1);
            }
            if (nh == 0)
                mma8(acc[4], a0, a1, a2, a3, bone, bone);
        }
    }

    // epilogue
    float* dst = g_pKV[ch][bh];
    #pragma unroll
    for (int i = 0; i < 4; i++){
        const int e = (nh*4 + i)*8 + 2*tig;
        *(float2*)(dst + (size_t)(d0+g  )*Dc + e) = make_float2(acc[i][0], acc[i][1]);
        *(float2*)(dst + (size_t)(d0+g+8)*Dc + e) = make_float2(acc[i][2], acc[i][3]);
    }
    if (nh == 0 && tig == 0){
        g_pKs[ch][bh][d0+g  ] = acc[4][0];
        g_pKs[ch][bh][d0+g+8] = acc[4][2];
    }
}

// ---------------------------------------------------------------------------
// Reduce partials (f32 out).
// ---------------------------------------------------------------------------
__global__ __launch_bounds__(256) void reduce_kernel(){
    const int bh = blockIdx.x, t = threadIdx.x;
    for (int i = t; i < Dc*Dc; i += 256){
        float s = 0.f;
        #pragma unroll
        for (int c = 0; c < NCHUNK; c++) s += g_pKV[c][bh][i];
        g_KV[bh][i] = s;
    }
    if (t < Dc){
        float s = 0.f;
        #pragma unroll
        for (int c = 0; c < NCHUNK; c++) s += g_pKs[c][bh][t];
        g_Ks[bh][t] = s;
    }
}

// ---------------------------------------------------------------------------
// Phase 2 (R8/R10-measured best, unchanged): out = Z * Qf @ KV.
// grid (BHc, 16), 256 threads, 256 s-rows/CTA (8 iters of 32).
// B-fragments register-resident (RNA). Q double-buffered, LDG prefetch ahead.
// Warp (h=w>>2, j=w&3): m-tile 16h, n-tiles {2j, 2j+1}.
// ---------------------------------------------------------------------------
__global__ __launch_bounds__(256, 4) void phase2_kernel(const float* __restrict__ Q,
                                                        float* __restrict__ out){
    __shared__ __align__(16) float sB[64][72];    // KV [d][e] raw f32
    __shared__ __align__(16) u32   sQd[2][32][68];// Qf RNA tf32 bits, double buffered
    __shared__ float sKs[64];
    __shared__ float sZ[2][32];

    const int bh = blockIdx.x, sb = blockIdx.y;
    const int t = threadIdx.x;
    const int warp = t >> 5, lane = t & 31;
    const int g = lane >> 2, tig = lane & 3;
    const int j = warp & 3, h = warp >> 2;

    // stage KV + Ksum once
    for (int i = t; i < Dc*Dc/4; i += 256){
        const int d = i >> 4, e4 = (i & 15) * 4;
        *(float4*)&sB[d][e4] = *(const float4*)&g_KV[bh][(size_t)d*Dc + e4];
    }
    if (t < Dc) sKs[t] = g_Ks[bh][t];
    __syncthreads();

    // register-resident B fragments (RNA tf32), n-tiles 2j and 2j+1
    const int nt0 = 2*j, nt1 = 2*j + 1;
    u32 bf[8][4];
    #pragma unroll
    for (int ks = 0; ks < 8; ks++){
        const int k0 = ks*8;
        bf[ks][0] = to_tf32(sB[k0+tig  ][nt0*8+g]);
        bf[ks][1] = to_tf32(sB[k0+tig+4][nt0*8+g]);
        bf[ks][2] = to_tf32(sB[k0+tig  ][nt1*8+g]);
        bf[ks][3] = to_tf32(sB[k0+tig+4][nt1*8+g]);
    }

    const float* Qb = Q   + ((size_t)bh*Sc + (size_t)sb*256)*Dc;
    float*       Ob = out + ((size_t)bh*Sc + (size_t)sb*256)*Dc;

    const int srow = t >> 3;          // 0..31
    const int c8 = (t & 7) * 8;

    // prologue: stage tile 0
    {
        const float* qr = Qb + (size_t)srow*Dc + c8;
        float4 qa = *(const float4*)(qr);
        float4 qb = *(const float4*)(qr + 4);
        float f0 = feat(qa.x), f1 = feat(qa.y), f2 = feat(qa.z), f3 = feat(qa.w);
        float f4 = feat(qb.x), f5 = feat(qb.y), f6 = feat(qb.z), f7 = feat(qb.w);
        float dot = f0*sKs[c8] + f1*sKs[c8+1] + f2*sKs[c8+2] + f3*sKs[c8+3]
                  + f4*sKs[c8+4] + f5*sKs[c8+5] + f6*sKs[c8+6] + f7*sKs[c8+7];
        dot += __shfl_xor_sync(0xffffffffu, dot, 1);
        dot += __shfl_xor_sync(0xffffffffu, dot, 2);
        dot += __shfl_xor_sync(0xffffffffu, dot, 4);
        if ((t & 7) == 0) sZ[0][srow] = 1.f / dot;
        *(uint4*)&sQd[0][srow][c8]   = make_uint4(to_tf32(f0), to_tf32(f1), to_tf32(f2), to_tf32(f3));
        *(uint4*)&sQd[0][srow][c8+4] = make_uint4(to_tf32(f4), to_tf32(f5), to_tf32(f6), to_tf32(f7));
    }
    __syncthreads();

    #pragma unroll 1
    for (int it = 0; it < 8; it++){
        const int buf = it & 1;

        // issue next tile's loads before compute (latency overlap)
        float4 qa, qb;
        if (it < 7){
            const float* qr = Qb + (size_t)((it+1)*32 + srow)*Dc + c8;
            qa = *(const float4*)(qr);
            qb = *(const float4*)(qr + 4);
        }

        // --- mma on this warp's m-tile ---
        float acc[2][4];
        #pragma unroll
        for (int n = 0; n < 2; n++)
            #pragma unroll
            for (int i = 0; i < 4; i++) acc[n][i] = 0.f;

        const int m0 = 16*h;
        #pragma unroll
        for (int ks = 0; ks < 8; ks++){
            const int k0 = ks*8;
            u32 a0 = sQd[buf][m0+g  ][k0+tig  ];
            u32 a1 = sQd[buf][m0+g+8][k0+tig  ];
            u32 a2 = sQd[buf][m0+g  ][k0+tig+4];
            u32 a3 = sQd[buf][m0+g+8][k0+tig+4];
            mma8(acc[0], a0, a1, a2, a3, bf[ks][0], bf[ks][1]);
            mma8(acc[1], a0, a1, a2, a3, bf[ks][2], bf[ks][3]);
        }

        const float z0 = sZ[buf][m0+g];
        const float z1 = sZ[buf][m0+g+8];
        float* r0 = Ob + (size_t)(it*32 + m0 + g)*Dc;
        float* r1 = Ob + (size_t)(it*32 + m0 + g + 8)*Dc;
        *(float2*)(r0 + nt0*8 + 2*tig) = make_float2(acc[0][0]*z0, acc[0][1]*z0);
        *(float2*)(r1 + nt0*8 + 2*tig) = make_float2(acc[0][2]*z1, acc[0][3]*z1);
        *(float2*)(r0 + nt1*8 + 2*tig) = make_float2(acc[1][0]*z0, acc[1][1]*z0);
        *(float2*)(r1 + nt1*8 + 2*tig) = make_float2(acc[1][2]*z1, acc[1][3]*z1);

        // stage next tile into other buffer
        if (it < 7){
            float f0 = feat(qa.x), f1 = feat(qa.y), f2 = feat(qa.z), f3 = feat(qa.w);
            float f4 = feat(qb.x), f5 = feat(qb.y), f6 = feat(qb.z), f7 = feat(qb.w);
            float dot = f0*sKs[c8] + f1*sKs[c8+1] + f2*sKs[c8+2] + f3*sKs[c8+3]
                      + f4*sKs[c8+4] + f5*sKs[c8+5] + f6*sKs[c8+6] + f7*sKs[c8+7];
            dot += __shfl_xor_sync(0xffffffffu, dot, 1);
            dot += __shfl_xor_sync(0xffffffffu, dot, 2);
            dot += __shfl_xor_sync(0xffffffffu, dot, 4);
            if ((t & 7) == 0) sZ[buf^1][srow] = 1.f / dot;
            *(uint4*)&sQd[buf^1][srow][c8]   = make_uint4(to_tf32(f0), to_tf32(f1), to_tf32(f2), to_tf32(f3));
            *(uint4*)&sQd[buf^1][srow][c8+4] = make_uint4(to_tf32(f4), to_tf32(f5), to_tf32(f6), to_tf32(f7));
        }
        __syncthreads();
    }
}

// ---------------------------------------------------------------------------
extern "C" void kernel_launch(void* const* d_in, const int* in_sizes, int n_in,
                              void* d_out, int out_size){
    const float* Q    = (const float*)d_in[0];
    const float* K    = (const float*)d_in[1];
    const float* V    = (const float*)d_in[2];
    const float* mask = (const float*)d_in[3];
    float* out = (float*)d_out;

    phase1_kernel<<<dim3(BHc, NCHUNK), 256>>>(K, V, mask);
    reduce_kernel<<<BHc, 256>>>();
    phase2_kernel<<<dim3(BHc, 16), 256>>>(Q, out);
}

// round 12
// speedup vs baseline: 1.2490x; 1.2490x over previous
#include <cuda_runtime.h>

typedef unsigned int u32;

#define Sc 4096
#define Dc 64
#define BHc 64
#define NCHUNK 16
#define CHUNK (Sc/NCHUNK)   // 256
#define NB (CHUNK/32)       // 8 blocks of 32 s-rows

__device__ float g_pKV[NCHUNK][BHc][Dc*Dc];  // f32 partial KV
__device__ float g_pKs[NCHUNK][BHc][Dc];     // f32 partial Ksum
__device__ float g_KV[BHc][Dc*Dc];           // reduced KV (f32)
__device__ float g_Ks[BHc][Dc];              // reduced Ksum (f32)

__device__ __forceinline__ u32 to_tf32(float f){
    u32 r; asm("cvt.rna.tf32.f32 %0, %1;" : "=r"(r) : "f"(f)); return r;
}
__device__ __forceinline__ void mma8(float c[4], u32 a0, u32 a1, u32 a2, u32 a3,
                                     u32 b0, u32 b1){
    asm volatile("mma.sync.aligned.m16n8k8.row.col.f32.tf32.tf32.f32 "
        "{%0,%1,%2,%3}, {%4,%5,%6,%7}, {%8,%9}, {%0,%1,%2,%3};"
        : "+f"(c[0]), "+f"(c[1]), "+f"(c[2]), "+f"(c[3])
        : "r"(a0), "r"(a1), "r"(a2), "r"(a3), "r"(b0), "r"(b1));
}
__device__ __forceinline__ float feat(float x){
    return x > 0.f ? x + 1.f : __expf(x);
}
__device__ __forceinline__ u32 smem_u32(const void* p){
    u32 a; asm("{ .reg .u64 t; cvta.to.shared.u64 t, %1; cvt.u32.u64 %0, t; }" : "=r"(a) : "l"(p));
    return a;
}
__device__ __forceinline__ void cp16(u32 dst, const float* src){
    asm volatile("cp.async.cg.shared.global [%0], [%1], 16;" :: "r"(dst), "l"(src) : "memory");
}
#define CP_COMMIT() asm volatile("cp.async.commit_group;" ::: "memory")

// ---------------------------------------------------------------------------
// Phase 1 (R10-measured best, unchanged): partial KV = Kf^T V (+Ksum column).
// grid (BHc, NCHUNK), 256 threads = 8 warps. Warp w: d-tile (w>>1)*16,
// n-half w&1. K: staging-time RNA convert. V: smem raw (MMA RZ truncation).
// ---------------------------------------------------------------------------
__global__ __launch_bounds__(256, 5) void phase1_kernel(const float* __restrict__ K,
                                                        const float* __restrict__ V,
                                                        const float* __restrict__ M){
    __shared__ __align__(16) u32   sK[2][32][72];   // raw f32 -> tf32 bits in place
    __shared__ __align__(16) float sV[2][32][72];   // raw V + ones col 64

    const int bh = blockIdx.x, ch = blockIdx.y;
    const int t = threadIdx.x;
    const int warp = t >> 5, lane = t & 31;
    const int g = lane >> 2, tig = lane & 3;

    const float* Kp = K + ((size_t)bh*Sc + (size_t)ch*CHUNK)*Dc;
    const float* Vp = V + ((size_t)bh*Sc + (size_t)ch*CHUNK)*Dc;
    const float* Mp = M + (size_t)bh*Sc + (size_t)ch*CHUNK;

    if (t < 64){
        const int buf = t >> 5, r = t & 31;
        sV[buf][r][64] = 1.f;
        #pragma unroll
        for (int c = 65; c < 72; c++) sV[buf][r][c] = 0.f;
    }

    const int srow = t >> 3;          // 0..31
    const int c4a = (t & 7) * 4;
    const int c4b = c4a + 32;
    const u32 skb = smem_u32(&sK[0][0][0]);
    const u32 svb = smem_u32(&sV[0][0][0]);
    const u32 BUFB = 32*72*4;

    #pragma unroll
    for (int b = 0; b < 2; b++){
        const float* kr = Kp + (size_t)(b*32 + srow)*Dc;
        const float* vr = Vp + (size_t)(b*32 + srow)*Dc;
        const u32 kd = skb + b*BUFB + (srow*72)*4;
        const u32 vd = svb + b*BUFB + (srow*72)*4;
        cp16(kd + c4a*4, kr + c4a);  cp16(kd + c4b*4, kr + c4b);
        cp16(vd + c4a*4, vr + c4a);  cp16(vd + c4b*4, vr + c4b);
        CP_COMMIT();
    }

    float acc[5][4];
    #pragma unroll
    for (int n = 0; n < 5; n++)
        #pragma unroll
        for (int i = 0; i < 4; i++) acc[n][i] = 0.f;

    const int d0 = (warp >> 1) * 16;
    const int nh = warp & 1;

    #pragma unroll
    for (int b = 0; b < NB; b++){
        const int buf = b & 1;
        if (b < NB-1) asm volatile("cp.async.wait_group 1;" ::: "memory");
        else          asm volatile("cp.async.wait_group 0;" ::: "memory");
        __syncthreads();

        {
            const float m = __ldg(Mp + b*32 + srow);
            u32* ka = &sK[buf][srow][c4a];
            u32* kb = &sK[buf][srow][c4b];
            uint4 kx = *(uint4*)ka, ky = *(uint4*)kb;
            *(uint4*)ka = make_uint4(to_tf32(feat(__uint_as_float(kx.x))*m),
                                     to_tf32(feat(__uint_as_float(kx.y))*m),
                                     to_tf32(feat(__uint_as_float(kx.z))*m),
                                     to_tf32(feat(__uint_as_float(kx.w))*m));
            *(uint4*)kb = make_uint4(to_tf32(feat(__uint_as_float(ky.x))*m),
                                     to_tf32(feat(__uint_as_float(ky.y))*m),
                                     to_tf32(feat(__uint_as_float(ky.z))*m),
                                     to_tf32(feat(__uint_as_float(ky.w))*m));
        }
        __syncthreads();

        #pragma unroll
        for (int ks = 0; ks < 4; ks++){
            const int s0 = ks*8;
            u32 a0 = sK[buf][s0+tig  ][d0+g  ];
            u32 a1 = sK[buf][s0+tig  ][d0+g+8];
            u32 a2 = sK[buf][s0+tig+4][d0+g  ];
            u32 a3 = sK[buf][s0+tig+4][d0+g+8];
            if (nh == 0){
                #pragma unroll
                for (int i = 0; i < 4; i++){
                    u32 b0 = __float_as_uint(sV[buf][s0+tig  ][i*8+g]);
                    u32 b1 = __float_as_uint(sV[buf][s0+tig+4][i*8+g]);
                    mma8(acc[i], a0, a1, a2, a3, b0, b1);
                }
                u32 b0 = __float_as_uint(sV[buf][s0+tig  ][64+g]);
                u32 b1 = __float_as_uint(sV[buf][s0+tig+4][64+g]);
                mma8(acc[4], a0, a1, a2, a3, b0, b1);
            } else {
                #pragma unroll
                for (int i = 0; i < 4; i++){
                    u32 b0 = __float_as_uint(sV[buf][s0+tig  ][(4+i)*8+g]);
                    u32 b1 = __float_as_uint(sV[buf][s0+tig+4][(4+i)*8+g]);
                    mma8(acc[i], a0, a1, a2, a3, b0, b1);
                }
            }
        }
        __syncthreads();

        if (b + 2 < NB){
            const float* kr = Kp + (size_t)((b+2)*32 + srow)*Dc;
            const float* vr = Vp + (size_t)((b+2)*32 + srow)*Dc;
            const u32 kd = skb + buf*BUFB + (srow*72)*4;
            const u32 vd = svb + buf*BUFB + (srow*72)*4;
            cp16(kd + c4a*4, kr + c4a);  cp16(kd + c4b*4, kr + c4b);
            cp16(vd + c4a*4, vr + c4a);  cp16(vd + c4b*4, vr + c4b);
        }
        CP_COMMIT();
    }

    float* dst = g_pKV[ch][bh];
    #pragma unroll
    for (int i = 0; i < 4; i++){
        const int e = (nh*4 + i)*8 + 2*tig;
        *(float2*)(dst + (size_t)(d0+g  )*Dc + e) = make_float2(acc[i][0], acc[i][1]);
        *(float2*)(dst + (size_t)(d0+g+8)*Dc + e) = make_float2(acc[i][2], acc[i][3]);
    }
    if (nh == 0 && tig == 0){
        g_pKs[ch][bh][d0+g  ] = acc[4][0];
        g_pKs[ch][bh][d0+g+8] = acc[4][2];
    }
}

// ---------------------------------------------------------------------------
// Reduce partials (f32 out).
// ---------------------------------------------------------------------------
__global__ __launch_bounds__(256) void reduce_kernel(){
    const int bh = blockIdx.x, t = threadIdx.x;
    for (int i = t; i < Dc*Dc; i += 256){
        float s = 0.f;
        #pragma unroll
        for (int c = 0; c < NCHUNK; c++) s += g_pKV[c][bh][i];
        g_KV[bh][i] = s;
    }
    if (t < Dc){
        float s = 0.f;
        #pragma unroll
        for (int c = 0; c < NCHUNK; c++) s += g_pKs[c][bh][t];
        g_Ks[bh][t] = s;
    }
}

// ---------------------------------------------------------------------------
// Phase 2 (NEW: phase1-style cp.async pipeline): out = Z * Qf @ KV.
// grid (BHc, 16), 256 threads, 256 s-rows/CTA (8 iters of 32).
// Q: triple-buffered cp.async -> in-place convert (feat + Z shfl-dot + RNA).
// B-fragments register-resident (RNA). 2 syncs/iter.
// Warp (h=w>>2, j=w&3): m-tile 16h, n-tiles {2j, 2j+1}.
// ---------------------------------------------------------------------------
__global__ __launch_bounds__(256, 4) void phase2_kernel(const float* __restrict__ Q,
                                                        float* __restrict__ out){
    __shared__ __align__(16) float sB[64][72];    // KV [d][e] raw f32
    __shared__ __align__(16) u32   sQ[3][32][72]; // Q raw -> tf32 bits in place
    __shared__ float sKs[64];
    __shared__ float sZ[3][32];

    const int bh = blockIdx.x, sb = blockIdx.y;
    const int t = threadIdx.x;
    const int warp = t >> 5, lane = t & 31;
    const int g = lane >> 2, tig = lane & 3;
    const int j = warp & 3, h = warp >> 2;

    // stage KV + Ksum once
    for (int i = t; i < Dc*Dc/4; i += 256){
        const int d = i >> 4, e4 = (i & 15) * 4;
        *(float4*)&sB[d][e4] = *(const float4*)&g_KV[bh][(size_t)d*Dc + e4];
    }
    if (t < Dc) sKs[t] = g_Ks[bh][t];

    const float* Qb = Q   + ((size_t)bh*Sc + (size_t)sb*256)*Dc;
    float*       Ob = out + ((size_t)bh*Sc + (size_t)sb*256)*Dc;

    const int srow = t >> 3;          // 0..31
    const int c8 = (t & 7) * 8;
    const u32 sqb = smem_u32(&sQ[0][0][0]);
    const u32 QBUF = 32*72*4;

    // prologue: prefetch Q tiles 0,1
    #pragma unroll
    for (int b = 0; b < 2; b++){
        const float* qr = Qb + (size_t)(b*32 + srow)*Dc + c8;
        const u32 qd = sqb + b*QBUF + (srow*72 + c8)*4;
        cp16(qd,      qr);
        cp16(qd + 16, qr + 4);
        CP_COMMIT();
    }
    __syncthreads();   // sB/sKs ready (also covered by later syncs)

    // register-resident B fragments (RNA tf32), n-tiles 2j and 2j+1
    const int nt0 = 2*j, nt1 = 2*j + 1;
    u32 bf[8][4];
    #pragma unroll
    for (int ks = 0; ks < 8; ks++){
        const int k0 = ks*8;
        bf[ks][0] = to_tf32(sB[k0+tig  ][nt0*8+g]);
        bf[ks][1] = to_tf32(sB[k0+tig+4][nt0*8+g]);
        bf[ks][2] = to_tf32(sB[k0+tig  ][nt1*8+g]);
        bf[ks][3] = to_tf32(sB[k0+tig+4][nt1*8+g]);
    }

    #pragma unroll 1
    for (int it = 0; it < 8; it++){
        const int buf = it % 3;
        asm volatile("cp.async.wait_group 1;" ::: "memory");
        __syncthreads();

        // prefetch it+2 into (it+2)%3 (= buffer of it-1; free after entry sync)
        if (it + 2 < 8){
            const float* qr = Qb + (size_t)((it+2)*32 + srow)*Dc + c8;
            const u32 qd = sqb + ((it+2)%3)*QBUF + (srow*72 + c8)*4;
            cp16(qd,      qr);
            cp16(qd + 16, qr + 4);
        }
        CP_COMMIT();   // uniform commit per iter

        // in-place convert: feat + Z shfl-dot (f32) + RNA tf32 bits
        {
            u32* qp = &sQ[buf][srow][c8];
            uint4 qx = *(uint4*)qp, qy = *(uint4*)(qp + 4);
            float f0 = feat(__uint_as_float(qx.x)), f1 = feat(__uint_as_float(qx.y));
            float f2 = feat(__uint_as_float(qx.z)), f3 = feat(__uint_as_float(qx.w));
            float f4 = feat(__uint_as_float(qy.x)), f5 = feat(__uint_as_float(qy.y));
            float f6 = feat(__uint_as_float(qy.z)), f7 = feat(__uint_as_float(qy.w));
            float dot = f0*sKs[c8] + f1*sKs[c8+1] + f2*sKs[c8+2] + f3*sKs[c8+3]
                      + f4*sKs[c8+4] + f5*sKs[c8+5] + f6*sKs[c8+6] + f7*sKs[c8+7];
            dot += __shfl_xor_sync(0xffffffffu, dot, 1);
            dot += __shfl_xor_sync(0xffffffffu, dot, 2);
            dot += __shfl_xor_sync(0xffffffffu, dot, 4);
            if ((t & 7) == 0) sZ[buf][srow] = 1.f / dot;
            *(uint4*)qp       = make_uint4(to_tf32(f0), to_tf32(f1), to_tf32(f2), to_tf32(f3));
            *(uint4*)(qp + 4) = make_uint4(to_tf32(f4), to_tf32(f5), to_tf32(f6), to_tf32(f7));
        }
        __syncthreads();

        // --- pure LDS + MMA on this warp's m-tile ---
        float acc[2][4];
        #pragma unroll
        for (int n = 0; n < 2; n++)
            #pragma unroll
            for (int i = 0; i < 4; i++) acc[n][i] = 0.f;

        const int m0 = 16*h;
        #pragma unroll
        for (int ks = 0; ks < 8; ks++){
            const int k0 = ks*8;
            u32 a0 = sQ[buf][m0+g  ][k0+tig  ];
            u32 a1 = sQ[buf][m0+g+8][k0+tig  ];
            u32 a2 = sQ[buf][m0+g  ][k0+tig+4];
            u32 a3 = sQ[buf][m0+g+8][k0+tig+4];
            mma8(acc[0], a0, a1, a2, a3, bf[ks][0], bf[ks][1]);
            mma8(acc[1], a0, a1, a2, a3, bf[ks][2], bf[ks][3]);
        }

        const float z0 = sZ[buf][m0+g];
        const float z1 = sZ[buf][m0+g+8];
        float* r0 = Ob + (size_t)(it*32 + m0 + g)*Dc;
        float* r1 = Ob + (size_t)(it*32 + m0 + g + 8)*Dc;
        *(float2*)(r0 + nt0*8 + 2*tig) = make_float2(acc[0][0]*z0, acc[0][1]*z0);
        *(float2*)(r1 + nt0*8 + 2*tig) = make_float2(acc[0][2]*z1, acc[0][3]*z1);
        *(float2*)(r0 + nt1*8 + 2*tig) = make_float2(acc[1][0]*z0, acc[1][1]*z0);
        *(float2*)(r1 + nt1*8 + 2*tig) = make_float2(acc[1][2]*z1, acc[1][3]*z1);
    }
}

// ---------------------------------------------------------------------------
extern "C" void kernel_launch(void* const* d_in, const int* in_sizes, int n_in,
                              void* d_out, int out_size){
    const float* Q    = (const float*)d_in[0];
    const float* K    = (const float*)d_in[1];
    const float* V    = (const float*)d_in[2];
    const float* mask = (const float*)d_in[3];
    float* out = (float*)d_out;

    phase1_kernel<<<dim3(BHc, NCHUNK), 256>>>(K, V, mask);
    reduce_kernel<<<BHc, 256>>>();
    phase2_kernel<<<dim3(BHc, 16), 256>>>(Q, out);
}

// round 13
// speedup vs baseline: 1.4662x; 1.1739x over previous
#include <cuda_runtime.h>

typedef unsigned int u32;

#define Sc 4096
#define Dc 64
#define BHc 64
#define NCHUNK 16
#define CHUNK (Sc/NCHUNK)   // 256
#define NB (CHUNK/32)       // 8 blocks of 32 s-rows

__device__ float g_pKV[NCHUNK][BHc][Dc*Dc];  // f32 partial KV
__device__ float g_pKs[NCHUNK][BHc][Dc];     // f32 partial Ksum
__device__ float g_KV[BHc][Dc*Dc];           // reduced KV (f32)
__device__ float g_Ks[BHc][Dc];              // reduced Ksum (f32)

__device__ __forceinline__ u32 to_tf32(float f){
    u32 r; asm("cvt.rna.tf32.f32 %0, %1;" : "=r"(r) : "f"(f)); return r;
}
__device__ __forceinline__ void mma8(float c[4], u32 a0, u32 a1, u32 a2, u32 a3,
                                     u32 b0, u32 b1){
    asm volatile("mma.sync.aligned.m16n8k8.row.col.f32.tf32.tf32.f32 "
        "{%0,%1,%2,%3}, {%4,%5,%6,%7}, {%8,%9}, {%0,%1,%2,%3};"
        : "+f"(c[0]), "+f"(c[1]), "+f"(c[2]), "+f"(c[3])
        : "r"(a0), "r"(a1), "r"(a2), "r"(a3), "r"(b0), "r"(b1));
}
__device__ __forceinline__ float feat(float x){
    return x > 0.f ? x + 1.f : __expf(x);
}
__device__ __forceinline__ u32 smem_u32(const void* p){
    u32 a; asm("{ .reg .u64 t; cvta.to.shared.u64 t, %1; cvt.u32.u64 %0, t; }" : "=r"(a) : "l"(p));
    return a;
}
__device__ __forceinline__ void cp16(u32 dst, const float* src){
    asm volatile("cp.async.cg.shared.global [%0], [%1], 16;" :: "r"(dst), "l"(src) : "memory");
}
#define CP_COMMIT() asm volatile("cp.async.commit_group;" ::: "memory")

// ---------------------------------------------------------------------------
// Phase 1: partial KV = Kf^T V (+Ksum column). grid (BHc, NCHUNK), 256 thr.
// Warp w: d-tile (w>>1)*16, n-half w&1. K: staging RNA convert (own-data,
// immediately after wait_group — no pre-convert barrier). V: smem raw (RZ).
// 2 syncs per iteration.
// ---------------------------------------------------------------------------
__global__ __launch_bounds__(256, 5) void phase1_kernel(const float* __restrict__ K,
                                                        const float* __restrict__ V,
                                                        const float* __restrict__ M){
    __shared__ __align__(16) u32   sK[2][32][72];   // raw f32 -> tf32 bits in place
    __shared__ __align__(16) float sV[2][32][72];   // raw V + ones col 64

    const int bh = blockIdx.x, ch = blockIdx.y;
    const int t = threadIdx.x;
    const int warp = t >> 5, lane = t & 31;
    const int g = lane >> 2, tig = lane & 3;

    const float* Kp = K + ((size_t)bh*Sc + (size_t)ch*CHUNK)*Dc;
    const float* Vp = V + ((size_t)bh*Sc + (size_t)ch*CHUNK)*Dc;
    const float* Mp = M + (size_t)bh*Sc + (size_t)ch*CHUNK;

    if (t < 64){
        const int buf = t >> 5, r = t & 31;
        sV[buf][r][64] = 1.f;
        #pragma unroll
        for (int c = 65; c < 72; c++) sV[buf][r][c] = 0.f;
    }

    const int srow = t >> 3;          // 0..31
    const int c4a = (t & 7) * 4;
    const int c4b = c4a + 32;
    const u32 skb = smem_u32(&sK[0][0][0]);
    const u32 svb = smem_u32(&sV[0][0][0]);
    const u32 BUFB = 32*72*4;

    #pragma unroll
    for (int b = 0; b < 2; b++){
        const float* kr = Kp + (size_t)(b*32 + srow)*Dc;
        const float* vr = Vp + (size_t)(b*32 + srow)*Dc;
        const u32 kd = skb + b*BUFB + (srow*72)*4;
        const u32 vd = svb + b*BUFB + (srow*72)*4;
        cp16(kd + c4a*4, kr + c4a);  cp16(kd + c4b*4, kr + c4b);
        cp16(vd + c4a*4, vr + c4a);  cp16(vd + c4b*4, vr + c4b);
        CP_COMMIT();
    }

    float acc[5][4];
    #pragma unroll
    for (int n = 0; n < 5; n++)
        #pragma unroll
        for (int i = 0; i < 4; i++) acc[n][i] = 0.f;

    const int d0 = (warp >> 1) * 16;
    const int nh = warp & 1;

    #pragma unroll
    for (int b = 0; b < NB; b++){
        const int buf = b & 1;
        if (b < NB-1) asm volatile("cp.async.wait_group 1;" ::: "memory");
        else          asm volatile("cp.async.wait_group 0;" ::: "memory");

        // convert own-thread K data (visible after wait_group; no barrier yet)
        {
            const float m = __ldg(Mp + b*32 + srow);
            u32* ka = &sK[buf][srow][c4a];
            u32* kb = &sK[buf][srow][c4b];
            uint4 kx = *(uint4*)ka, ky = *(uint4*)kb;
            *(uint4*)ka = make_uint4(to_tf32(feat(__uint_as_float(kx.x))*m),
                                     to_tf32(feat(__uint_as_float(kx.y))*m),
                                     to_tf32(feat(__uint_as_float(kx.z))*m),
                                     to_tf32(feat(__uint_as_float(kx.w))*m));
            *(uint4*)kb = make_uint4(to_tf32(feat(__uint_as_float(ky.x))*m),
                                     to_tf32(feat(__uint_as_float(ky.y))*m),
                                     to_tf32(feat(__uint_as_float(ky.z))*m),
                                     to_tf32(feat(__uint_as_float(ky.w))*m));
        }
        __syncthreads();   // converted K + raw V visible to all warps

        #pragma unroll
        for (int ks = 0; ks < 4; ks++){
            const int s0 = ks*8;
            u32 a0 = sK[buf][s0+tig  ][d0+g  ];
            u32 a1 = sK[buf][s0+tig  ][d0+g+8];
            u32 a2 = sK[buf][s0+tig+4][d0+g  ];
            u32 a3 = sK[buf][s0+tig+4][d0+g+8];
            if (nh == 0){
                #pragma unroll
                for (int i = 0; i < 4; i++){
                    u32 b0 = __float_as_uint(sV[buf][s0+tig  ][i*8+g]);
                    u32 b1 = __float_as_uint(sV[buf][s0+tig+4][i*8+g]);
                    mma8(acc[i], a0, a1, a2, a3, b0, b1);
                }
                u32 b0 = __float_as_uint(sV[buf][s0+tig  ][64+g]);
                u32 b1 = __float_as_uint(sV[buf][s0+tig+4][64+g]);
                mma8(acc[4], a0, a1, a2, a3, b0, b1);
            } else {
                #pragma unroll
                for (int i = 0; i < 4; i++){
                    u32 b0 = __float_as_uint(sV[buf][s0+tig  ][(4+i)*8+g]);
                    u32 b1 = __float_as_uint(sV[buf][s0+tig+4][(4+i)*8+g]);
                    mma8(acc[i], a0, a1, a2, a3, b0, b1);
                }
            }
        }
        __syncthreads();   // buf free for refill

        if (b + 2 < NB){
            const float* kr = Kp + (size_t)((b+2)*32 + srow)*Dc;
            const float* vr = Vp + (size_t)((b+2)*32 + srow)*Dc;
            const u32 kd = skb + buf*BUFB + (srow*72)*4;
            const u32 vd = svb + buf*BUFB + (srow*72)*4;
            cp16(kd + c4a*4, kr + c4a);  cp16(kd + c4b*4, kr + c4b);
            cp16(vd + c4a*4, vr + c4a);  cp16(vd + c4b*4, vr + c4b);
        }
        CP_COMMIT();
    }

    float* dst = g_pKV[ch][bh];
    #pragma unroll
    for (int i = 0; i < 4; i++){
        const int e = (nh*4 + i)*8 + 2*tig;
        *(float2*)(dst + (size_t)(d0+g  )*Dc + e) = make_float2(acc[i][0], acc[i][1]);
        *(float2*)(dst + (size_t)(d0+g+8)*Dc + e) = make_float2(acc[i][2], acc[i][3]);
    }
    if (nh == 0 && tig == 0){
        g_pKs[ch][bh][d0+g  ] = acc[4][0];
        g_pKs[ch][bh][d0+g+8] = acc[4][2];
    }
}

// ---------------------------------------------------------------------------
// Reduce partials, parallel: grid (BHc, 16), 256 threads. CTA (bh, part)
// sums 256 KV elements; part 0 also reduces Ksum.
// ---------------------------------------------------------------------------
__global__ __launch_bounds__(256) void reduce_kernel(){
    const int bh = blockIdx.x, part = blockIdx.y;
    const int t = threadIdx.x;
    const int i = part*256 + t;
    float s = 0.f;
    #pragma unroll
    for (int c = 0; c < NCHUNK; c++) s += g_pKV[c][bh][i];
    g_KV[bh][i] = s;
    if (part == 0 && t < Dc){
        float k = 0.f;
        #pragma unroll
        for (int c = 0; c < NCHUNK; c++) k += g_pKs[c][bh][t];
        g_Ks[bh][t] = k;
    }
}

// ---------------------------------------------------------------------------
// Phase 2 (R10-measured best, unchanged): out = Z * Qf @ KV.
// grid (BHc, 16), 256 threads, 256 s-rows/CTA (8 iters of 32).
// B-fragments register-resident (RNA). Q double-buffered, LDG prefetch ahead.
// Warp (h=w>>2, j=w&3): m-tile 16h, n-tiles {2j, 2j+1}.
// ---------------------------------------------------------------------------
__global__ __launch_bounds__(256, 4) void phase2_kernel(const float* __restrict__ Q,
                                                        float* __restrict__ out){
    __shared__ __align__(16) float sB[64][72];    // KV [d][e] raw f32
    __shared__ __align__(16) u32   sQd[2][32][68];// Qf RNA tf32 bits, double buffered
    __shared__ float sKs[64];
    __shared__ float sZ[2][32];

    const int bh = blockIdx.x, sb = blockIdx.y;
    const int t = threadIdx.x;
    const int warp = t >> 5, lane = t & 31;
    const int g = lane >> 2, tig = lane & 3;
    const int j = warp & 3, h = warp >> 2;

    // stage KV + Ksum once
    for (int i = t; i < Dc*Dc/4; i += 256){
        const int d = i >> 4, e4 = (i & 15) * 4;
        *(float4*)&sB[d][e4] = *(const float4*)&g_KV[bh][(size_t)d*Dc + e4];
    }
    if (t < Dc) sKs[t] = g_Ks[bh][t];
    __syncthreads();

    // register-resident B fragments (RNA tf32), n-tiles 2j and 2j+1
    const int nt0 = 2*j, nt1 = 2*j + 1;
    u32 bf[8][4];
    #pragma unroll
    for (int ks = 0; ks < 8; ks++){
        const int k0 = ks*8;
        bf[ks][0] = to_tf32(sB[k0+tig  ][nt0*8+g]);
        bf[ks][1] = to_tf32(sB[k0+tig+4][nt0*8+g]);
        bf[ks][2] = to_tf32(sB[k0+tig  ][nt1*8+g]);
        bf[ks][3] = to_tf32(sB[k0+tig+4][nt1*8+g]);
    }

    const float* Qb = Q   + ((size_t)bh*Sc + (size_t)sb*256)*Dc;
    float*       Ob = out + ((size_t)bh*Sc + (size_t)sb*256)*Dc;

    const int srow = t >> 3;          // 0..31
    const int c8 = (t & 7) * 8;

    // prologue: stage tile 0
    {
        const float* qr = Qb + (size_t)srow*Dc + c8;
        float4 qa = *(const float4*)(qr);
        float4 qb = *(const float4*)(qr + 4);
        float f0 = feat(qa.x), f1 = feat(qa.y), f2 = feat(qa.z), f3 = feat(qa.w);
        float f4 = feat(qb.x), f5 = feat(qb.y), f6 = feat(qb.z), f7 = feat(qb.w);
        float dot = f0*sKs[c8] + f1*sKs[c8+1] + f2*sKs[c8+2] + f3*sKs[c8+3]
                  + f4*sKs[c8+4] + f5*sKs[c8+5] + f6*sKs[c8+6] + f7*sKs[c8+7];
        dot += __shfl_xor_sync(0xffffffffu, dot, 1);
        dot += __shfl_xor_sync(0xffffffffu, dot, 2);
        dot += __shfl_xor_sync(0xffffffffu, dot, 4);
        if ((t & 7) == 0) sZ[0][srow] = 1.f / dot;
        *(uint4*)&sQd[0][srow][c8]   = make_uint4(to_tf32(f0), to_tf32(f1), to_tf32(f2), to_tf32(f3));
        *(uint4*)&sQd[0][srow][c8+4] = make_uint4(to_tf32(f4), to_tf32(f5), to_tf32(f6), to_tf32(f7));
    }
    __syncthreads();

    #pragma unroll 1
    for (int it = 0; it < 8; it++){
        const int buf = it & 1;

        // issue next tile's loads before compute (latency overlap)
        float4 qa, qb;
        if (it < 7){
            const float* qr = Qb + (size_t)((it+1)*32 + srow)*Dc + c8;
            qa = *(const float4*)(qr);
            qb = *(const float4*)(qr + 4);
        }

        // --- mma on this warp's m-tile ---
        float acc[2][4];
        #pragma unroll
        for (int n = 0; n < 2; n++)
            #pragma unroll
            for (int i = 0; i < 4; i++) acc[n][i] = 0.f;

        const int m0 = 16*h;
        #pragma unroll
        for (int ks = 0; ks < 8; ks++){
            const int k0 = ks*8;
            u32 a0 = sQd[buf][m0+g  ][k0+tig  ];
            u32 a1 = sQd[buf][m0+g+8][k0+tig  ];
            u32 a2 = sQd[buf][m0+g  ][k0+tig+4];
            u32 a3 = sQd[buf][m0+g+8][k0+tig+4];
            mma8(acc[0], a0, a1, a2, a3, bf[ks][0], bf[ks][1]);
            mma8(acc[1], a0, a1, a2, a3, bf[ks][2], bf[ks][3]);
        }

        const float z0 = sZ[buf][m0+g];
        const float z1 = sZ[buf][m0+g+8];
        float* r0 = Ob + (size_t)(it*32 + m0 + g)*Dc;
        float* r1 = Ob + (size_t)(it*32 + m0 + g + 8)*Dc;
        *(float2*)(r0 + nt0*8 + 2*tig) = make_float2(acc[0][0]*z0, acc[0][1]*z0);
        *(float2*)(r1 + nt0*8 + 2*tig) = make_float2(acc[0][2]*z1, acc[0][3]*z1);
        *(float2*)(r0 + nt1*8 + 2*tig) = make_float2(acc[1][0]*z0, acc[1][1]*z0);
        *(float2*)(r1 + nt1*8 + 2*tig) = make_float2(acc[1][2]*z1, acc[1][3]*z1);

        // stage next tile into other buffer
        if (it < 7){
            float f0 = feat(qa.x), f1 = feat(qa.y), f2 = feat(qa.z), f3 = feat(qa.w);
            float f4 = feat(qb.x), f5 = feat(qb.y), f6 = feat(qb.z), f7 = feat(qb.w);
            float dot = f0*sKs[c8] + f1*sKs[c8+1] + f2*sKs[c8+2] + f3*sKs[c8+3]
                      + f4*sKs[c8+4] + f5*sKs[c8+5] + f6*sKs[c8+6] + f7*sKs[c8+7];
            dot += __shfl_xor_sync(0xffffffffu, dot, 1);
            dot += __shfl_xor_sync(0xffffffffu, dot, 2);
            dot += __shfl_xor_sync(0xffffffffu, dot, 4);
            if ((t & 7) == 0) sZ[buf^1][srow] = 1.f / dot;
            *(uint4*)&sQd[buf^1][srow][c8]   = make_uint4(to_tf32(f0), to_tf32(f1), to_tf32(f2), to_tf32(f3));
            *(uint4*)&sQd[buf^1][srow][c8+4] = make_uint4(to_tf32(f4), to_tf32(f5), to_tf32(f6), to_tf32(f7));
        }
        __syncthreads();
    }
}

// ---------------------------------------------------------------------------
extern "C" void kernel_launch(void* const* d_in, const int* in_sizes, int n_in,
                              void* d_out, int out_size){
    const float* Q    = (const float*)d_in[0];
    const float* K    = (const float*)d_in[1];
    const float* V    = (const float*)d_in[2];
    const float* mask = (const float*)d_in[3];
    float* out = (float*)d_out;

    phase1_kernel<<<dim3(BHc, NCHUNK), 256>>>(K, V, mask);
    reduce_kernel<<<dim3(BHc, 16), 256>>>();
    phase2_kernel<<<dim3(BHc, 16), 256>>>(Q, out);
}